// round 6
// baseline (speedup 1.0000x reference)
#include <cuda_runtime.h>

#define NN 100000
#define NE 3200000
#define H  64
#define SCAN_B 1024
#define NB ((NN + SCAN_B - 1) / SCAN_B)   // 98

// -------- device scratch (no allocations allowed) --------
__device__ int   g_cnt[NN];
__device__ int   g_row[NN + 1];
__device__ int   g_pos[NN];
__device__ float g_dis[NN];
__device__ int   g_bsum[NB];
__device__ int   g_boff[NB];
__device__ int   g_cs[NE];        // CSR: src node per slot
__device__ float g_cw[NE];        // CSR: dis[s]*dis[d] per slot
__device__ float g_tmp[NN * H];   // aggregated h1 (64-dim)
__device__ float g_h  [NN * H];   // h1 node features
__device__ float g_P  [NN * H];   // h2 @ Wm1[0:64] + bm1
__device__ float g_Q  [NN * H];   // h2 @ Wm1[64:128]

// -------- CSR build --------
__global__ void k_zero_cnt() {
    int i = blockIdx.x * blockDim.x + threadIdx.x;
    if (i < NN) g_cnt[i] = 0;
}

__global__ void k_hist(const int* __restrict__ dst) {
    int e = blockIdx.x * blockDim.x + threadIdx.x;
    if (e < NE) atomicAdd(&g_cnt[dst[e]], 1);
}

__global__ void k_scan1() {
    __shared__ int ss[SCAN_B];
    int tid = threadIdx.x;
    int i = blockIdx.x * SCAN_B + tid;
    int v = (i < NN) ? g_cnt[i] : 0;
    ss[tid] = v;
    __syncthreads();
#pragma unroll
    for (int off = 1; off < SCAN_B; off <<= 1) {
        int t = (tid >= off) ? ss[tid - off] : 0;
        __syncthreads();
        ss[tid] += t;
        __syncthreads();
    }
    if (i < NN) g_row[i] = ss[tid] - v;
    if (tid == SCAN_B - 1) g_bsum[blockIdx.x] = ss[tid];
}

__global__ void k_scan2() {
    __shared__ int ss[128];
    int tid = threadIdx.x;
    int v = (tid < NB) ? g_bsum[tid] : 0;
    ss[tid] = v;
    __syncthreads();
#pragma unroll
    for (int off = 1; off < 128; off <<= 1) {
        int t = (tid >= off) ? ss[tid - off] : 0;
        __syncthreads();
        ss[tid] += t;
        __syncthreads();
    }
    if (tid < NB) g_boff[tid] = ss[tid] - v;
}

__global__ void k_scan3() {
    int i = blockIdx.x * SCAN_B + threadIdx.x;
    if (i < NN) {
        int r = g_row[i] + g_boff[blockIdx.x];
        g_row[i] = r;
        g_pos[i] = r;
        g_dis[i] = rsqrtf((float)(g_cnt[i] + 1));   // +1 self-loop
    }
    if (i == 0) g_row[NN] = NE;
}

__global__ void k_place(const int* __restrict__ src, const int* __restrict__ dst) {
    int e = blockIdx.x * blockDim.x + threadIdx.x;
    if (e >= NE) return;
    int s = src[e], d = dst[e];
    int idx = atomicAdd(&g_pos[d], 1);
    g_cs[idx] = s;
    g_cw[idx] = g_dis[s] * g_dis[d];
}

// -------- fused layer 1: warp per node --------
// ax = sum_edges w*x[s] + dis^2*x[n] (4-dim), then h1 = relu(ax@W1 + b1)
__global__ void k_aggx_h1(const float* __restrict__ x,
                          const float* __restrict__ W1, const float* __restrict__ b1) {
    int w = (blockIdx.x * blockDim.x + threadIdx.x) >> 5;
    if (w >= NN) return;
    int lane = threadIdx.x & 31;
    int r0 = g_row[w], r1 = g_row[w + 1];
    float ax = 0.f, ay = 0.f, az = 0.f, aw = 0.f;
    for (int r = r0 + lane; r < r1; r += 32) {
        int s = g_cs[r];
        float ww = g_cw[r];
        float4 xv = *reinterpret_cast<const float4*>(x + (size_t)s * 4);
        ax += xv.x * ww; ay += xv.y * ww; az += xv.z * ww; aw += xv.w * ww;
    }
    if (lane == 0) {                     // self-loop term, once
        float dd = g_dis[w]; dd *= dd;
        float4 xv = *reinterpret_cast<const float4*>(x + (size_t)w * 4);
        ax += dd * xv.x; ay += dd * xv.y; az += dd * xv.z; aw += dd * xv.w;
    }
#pragma unroll
    for (int off = 16; off >= 1; off >>= 1) {   // xor: all lanes end with total
        ax += __shfl_xor_sync(0xffffffffu, ax, off);
        ay += __shfl_xor_sync(0xffffffffu, ay, off);
        az += __shfl_xor_sync(0xffffffffu, az, off);
        aw += __shfl_xor_sync(0xffffffffu, aw, off);
    }
    // dense: each lane computes 2 output columns
    size_t o = (size_t)w * H;
#pragma unroll
    for (int half = 0; half < 2; half++) {
        int c = lane + half * 32;
        float s = ax * __ldg(W1 + c) + ay * __ldg(W1 + 64 + c)
                + az * __ldg(W1 + 128 + c) + aw * __ldg(W1 + 192 + c) + __ldg(b1 + c);
        g_h[o + c] = fmaxf(s, 0.f);
    }
}

// -------- layer-2 aggregation (64-dim): tmp[n] = sum w*h1[s] + dis^2*h1[n] --------
// one warp per node, float2 per lane (columns 2*lane, 2*lane+1)
__global__ void k_agg64() {
    int w = (blockIdx.x * blockDim.x + threadIdx.x) >> 5;
    if (w >= NN) return;
    int lane = threadIdx.x & 31;
    int r = g_row[w], r1 = g_row[w + 1];
    const float2* hp = reinterpret_cast<const float2*>(g_h);
    float a0 = 0.f, a1 = 0.f;
    for (; r + 1 < r1; r += 2) {
        int   s0 = g_cs[r],  s1 = g_cs[r + 1];
        float w0 = g_cw[r],  w1 = g_cw[r + 1];
        float2 v0 = hp[(size_t)s0 * 32 + lane];
        float2 v1 = hp[(size_t)s1 * 32 + lane];
        a0 += v0.x * w0; a1 += v0.y * w0;
        a0 += v1.x * w1; a1 += v1.y * w1;
    }
    if (r < r1) {
        int s = g_cs[r]; float ww = g_cw[r];
        float2 v = hp[(size_t)s * 32 + lane];
        a0 += v.x * ww; a1 += v.y * ww;
    }
    float dd = g_dis[w]; dd *= dd;
    float2 v = hp[(size_t)w * 32 + lane];
    a0 += v.x * dd; a1 += v.y * dd;
    float2 o; o.x = a0; o.y = a1;
    reinterpret_cast<float2*>(g_tmp)[(size_t)w * 32 + lane] = o;
}

// -------- fused node-dense: h2 = relu(tmp@W2+b2) (smem only), then --------
// P = h2@Wm1[0:64] + bm1, Q = h2@Wm1[64:128].  16 nodes / block, 256 thr.
__global__ void k_dense2(const float* __restrict__ W2, const float* __restrict__ b2,
                         const float* __restrict__ Wm1, const float* __restrict__ bm1) {
    __shared__ float sbuf[9216];      // [0:4096) W-tile A, [4096:8192) W-tile B, [8192:9216) node tile
    float* sWa = sbuf;
    float* sWb = sbuf + 4096;
    float* sIn = sbuf + 8192;
    int tid = threadIdx.x;
    int nb = blockIdx.x * 16;
    // stage 1: W2 in sWa, input tile in sIn
    for (int i = tid; i < 4096; i += 256) sWa[i] = W2[i];
    for (int i = tid; i < 1024; i += 256) sIn[i] = g_tmp[nb * 64 + i];
    __syncthreads();
    int col = tid & 63, ng = tid >> 6;
    float hreg[4];
    {
        float a[4] = {0.f, 0.f, 0.f, 0.f};
#pragma unroll 8
        for (int k = 0; k < 64; k++) {
            float wv = sWa[k * 64 + col];
#pragma unroll
            for (int m = 0; m < 4; m++) a[m] += sIn[(ng + 4 * m) * 64 + k] * wv;
        }
        float bb = __ldg(b2 + col);
#pragma unroll
        for (int m = 0; m < 4; m++) hreg[m] = fmaxf(a[m] + bb, 0.f);
    }
    __syncthreads();                   // everyone done reading sWa/sIn
    // stage 2: h2 into sIn, Wm1 halves into sWa/sWb
#pragma unroll
    for (int m = 0; m < 4; m++) sIn[(ng + 4 * m) * 64 + col] = hreg[m];
    for (int i = tid; i < 4096; i += 256) { sWa[i] = Wm1[i]; sWb[i] = Wm1[4096 + i]; }
    __syncthreads();
    float p[4] = {0.f, 0.f, 0.f, 0.f};
    float q[4] = {0.f, 0.f, 0.f, 0.f};
#pragma unroll 8
    for (int k = 0; k < 64; k++) {
        float wa = sWa[k * 64 + col];
        float wb = sWb[k * 64 + col];
#pragma unroll
        for (int m = 0; m < 4; m++) {
            float xv = sIn[(ng + 4 * m) * 64 + k];
            p[m] += xv * wa;
            q[m] += xv * wb;
        }
    }
    float bmv = __ldg(bm1 + col);
#pragma unroll
    for (int m = 0; m < 4; m++) {
        size_t o = (size_t)(nb + ng + 4 * m) * 64 + col;
        g_P[o] = p[m] + bmv;
        g_Q[o] = q[m];
    }
}

// -------- edge epilogue: out[e] = relu(P[s]+Q[d]+ea@Wea) @ Wm2 + bm2 --------
__global__ void k_edge(const int* __restrict__ src, const int* __restrict__ dst,
                       const float* __restrict__ ea,
                       const float* __restrict__ Wm1,
                       const float* __restrict__ Wm2, const float* __restrict__ bm2,
                       float* __restrict__ out) {
    int l  = threadIdx.x & 15;
    int c0 = l * 4;
    float4 w0 = *reinterpret_cast<const float4*>(Wm1 + 128 * 64 + c0);
    float4 w1 = *reinterpret_cast<const float4*>(Wm1 + 129 * 64 + c0);
    float4 w2 = *reinterpret_cast<const float4*>(Wm1 + 130 * 64 + c0);
    float4 w3 = *reinterpret_cast<const float4*>(Wm1 + 131 * 64 + c0);
    float4 wo = *reinterpret_cast<const float4*>(Wm2 + c0);
    float  ob = bm2[0];

    int grp  = (blockIdx.x * blockDim.x + threadIdx.x) >> 4;
    int ngrp = (gridDim.x * blockDim.x) >> 4;
    for (int e = grp; e < NE; e += ngrp) {
        int s = src[e], d = dst[e];
        float4 p = *reinterpret_cast<const float4*>(g_P + (size_t)s * 64 + c0);
        float4 q = *reinterpret_cast<const float4*>(g_Q + (size_t)d * 64 + c0);
        float4 a = *reinterpret_cast<const float4*>(ea + (size_t)e * 4);
        float z0 = p.x + q.x + a.x * w0.x + a.y * w1.x + a.z * w2.x + a.w * w3.x;
        float z1 = p.y + q.y + a.x * w0.y + a.y * w1.y + a.z * w2.y + a.w * w3.y;
        float z2 = p.z + q.z + a.x * w0.z + a.y * w1.z + a.z * w2.z + a.w * w3.z;
        float z3 = p.w + q.w + a.x * w0.w + a.y * w1.w + a.z * w2.w + a.w * w3.w;
        z0 = fmaxf(z0, 0.f); z1 = fmaxf(z1, 0.f); z2 = fmaxf(z2, 0.f); z3 = fmaxf(z3, 0.f);
        float part = z0 * wo.x + z1 * wo.y + z2 * wo.z + z3 * wo.w;
#pragma unroll
        for (int off = 8; off >= 1; off >>= 1)
            part += __shfl_down_sync(0xffffffffu, part, off, 16);
        if (l == 0) out[e] = part + ob;
    }
}

extern "C" void kernel_launch(void* const* d_in, const int* in_sizes, int n_in,
                              void* d_out, int out_size) {
    const float* x   = (const float*)d_in[0];
    const int*   ei  = (const int*)  d_in[1];   // [2, NE] int32
    const float* ea  = (const float*)d_in[2];
    const float* W1  = (const float*)d_in[3];
    const float* b1  = (const float*)d_in[4];
    const float* W2  = (const float*)d_in[5];
    const float* b2  = (const float*)d_in[6];
    const float* Wm1 = (const float*)d_in[7];
    const float* bm1 = (const float*)d_in[8];
    const float* Wm2 = (const float*)d_in[9];
    const float* bm2 = (const float*)d_in[10];
    float* out = (float*)d_out;

    const int* src = ei;
    const int* dst = ei + NE;

    const int TB = 256;
    int nn_blk  = (NN + TB - 1) / TB;
    int ne_blk  = (NE + TB - 1) / TB;
    int agg_blk = (NN + 7) / 8;                  // 8 warps (nodes) per block

    // CSR build + norm
    k_zero_cnt<<<nn_blk, TB>>>();
    k_hist<<<ne_blk, TB>>>(dst);
    k_scan1<<<NB, SCAN_B>>>();
    k_scan2<<<1, 128>>>();
    k_scan3<<<NB, SCAN_B>>>();
    k_place<<<ne_blk, TB>>>(src, dst);

    // layer 1 (fused agg + dense)
    k_aggx_h1<<<agg_blk, TB>>>(x, W1, b1);

    // layer 2 agg, then fused dense (h2 never materialized) -> P,Q
    k_agg64<<<agg_blk, TB>>>();
    k_dense2<<<NN / 16, TB>>>(W2, b2, Wm1, bm1);

    // edge epilogue
    k_edge<<<1184, TB>>>(src, dst, ea, Wm1, Wm2, bm2, out);
}